// round 15
// baseline (speedup 1.0000x reference)
#include <cuda_runtime.h>
#include <cuda_bf16.h>
#include <math.h>
#include <stdint.h>

// Problem constants
#define B_  16
#define S_  2048
#define H_  768
#define HH_ 384
#define C_  64
#define L_  4

// q pre-scale: alpha * log2(e) folded into the q projection output
#define QSCALE (1.4426950408889634f / 19.595917942265423f)

// ---------------- scratch (static __device__ arrays; no allocation) ----------
__device__ __nv_bfloat16 g_xhi [25165824];     // x bf16        [B*S,H]
__device__ __nv_bfloat16 g_qhi [12582912];     // q bf16 (prescaled) [B*S,HH]
__device__ __nv_bfloat16 g_khi [12582912];     // k bf16        [B*S,HH]
__device__ __nv_bfloat16 g_yhi [12582912];     // y bf16        [B*S,HH]
__device__ __nv_bfloat16 g_phi [67108864];     // p=exp(attn) bf16 [B,S,S]
__device__ unsigned long long g_Zq[32768];     // fixed-point row sums of p
__device__ __nv_bfloat16 g_yThi[12582912];     // y^T bf16      [B,HH,S]
__device__ float         g_hpre[12582912];     // h_pre (unnormalized) [B*S,HH]
__device__ float         g_ts  [32768];
__device__ float         g_pool[12288];
__device__ __nv_bfloat16 g_Wcat[884736];       // [Wq|Wk|W1]^T bf16 [1152,768]

// ============================ PTX helpers ====================================
__device__ __forceinline__ uint32_t smem_u32(const void* p) {
    return (uint32_t)__cvta_generic_to_shared(p);
}

__device__ __forceinline__ float ex2f(float x) {
    float r; asm("ex2.approx.f32 %0, %1;" : "=f"(r) : "f"(x)); return r;
}

__device__ __forceinline__ void cp16(uint32_t dst, const void* src) {
    asm volatile("cp.async.cg.shared.global [%0], [%1], 16;" :: "r"(dst), "l"(src));
}
#define CP_COMMIT() asm volatile("cp.async.commit_group;" ::: "memory")
#define CP_WAIT2()  asm volatile("cp.async.wait_group 2;" ::: "memory")

#define LDSM4(r, addr) \
    asm volatile("ldmatrix.sync.aligned.m8n8.x4.shared.b16 {%0,%1,%2,%3}, [%4];" \
        : "=r"((r)[0]), "=r"((r)[1]), "=r"((r)[2]), "=r"((r)[3]) : "r"(addr))

#define MMA16816(d, a, b) \
    asm volatile("mma.sync.aligned.m16n8k16.row.col.f32.bf16.bf16.f32 " \
        "{%0,%1,%2,%3}, {%4,%5,%6,%7}, {%8,%9}, {%0,%1,%2,%3};" \
        : "+f"((d)[0]), "+f"((d)[1]), "+f"((d)[2]), "+f"((d)[3]) \
        : "r"((a)[0]), "r"((a)[1]), "r"((a)[2]), "r"((a)[3]), \
          "r"((b)[0]), "r"((b)[1]))

// SMEM tile geometry: 128 rows x 32 bf16 (64B data) padded to 80B/row
#define LDSROW 80
#define TILEB  (128 * LDSROW)         // 10240 B
#define BUFB   (2 * TILEB)            // A, B tiles = 20480 B
#define GEMM_SMEM (3 * BUFB)          // 3-stage pipeline = 61440 B

#define ZSCALE 1048576.0f             // 2^20 fixed point for deterministic Z

// =============== conversions ================================================
__global__ __launch_bounds__(256)
void cvt_bf16_kernel(const float* __restrict__ src, __nv_bfloat16* __restrict__ hi)
{
    const size_t i = ((size_t)blockIdx.x * 256 + threadIdx.x) * 8;
    float4 v0 = *(const float4*)(src + i);
    float4 v1 = *(const float4*)(src + i + 4);
    __nv_bfloat16 h[8];
    h[0] = __float2bfloat16(v0.x); h[1] = __float2bfloat16(v0.y);
    h[2] = __float2bfloat16(v0.z); h[3] = __float2bfloat16(v0.w);
    h[4] = __float2bfloat16(v1.x); h[5] = __float2bfloat16(v1.y);
    h[6] = __float2bfloat16(v1.z); h[7] = __float2bfloat16(v1.w);
    *(uint4*)(hi + i) = *(const uint4*)h;
}

// Wq/Wk/W1 [768,384] fp32 -> concatenated W^T [1152,768] bf16 (z picks weight)
__global__ __launch_bounds__(256)
void transpose_w_kernel(const float* __restrict__ Wq, const float* __restrict__ Wk,
                        const float* __restrict__ W1, __nv_bfloat16* __restrict__ out)
{
    __shared__ float tile[32][33];
    const float* in = (blockIdx.z == 0) ? Wq : (blockIdx.z == 1) ? Wk : W1;
    __nv_bfloat16* o = out + (size_t)blockIdx.z * (HH_ * H_);
    const int r0 = blockIdx.x * 32, c0 = blockIdx.y * 32;
    const int tx = threadIdx.x, ty = threadIdx.y;
#pragma unroll
    for (int j = 0; j < 32; j += 8)
        tile[ty + j][tx] = in[(size_t)(r0 + ty + j) * HH_ + c0 + tx];
    __syncthreads();
    const int t = ty * 32 + tx;
#pragma unroll
    for (int pidx = t; pidx < 512; pidx += 256) {
        const int oc = pidx >> 4;
        const int pr = (pidx & 15) * 2;
        __nv_bfloat16 h[2];
        h[0] = __float2bfloat16(tile[pr][oc]);
        h[1] = __float2bfloat16(tile[pr + 1][oc]);
        size_t off = (size_t)(c0 + oc) * H_ + r0 + pr;
        *(uint32_t*)(o + off) = *(const uint32_t*)h;
    }
}

// bf16 in [R, C] -> bf16 out [C, R]; per-z offset = z*R*C
__global__ __launch_bounds__(256)
void transpose_bb_kernel(const __nv_bfloat16* __restrict__ in,
                         __nv_bfloat16* __restrict__ out, int R, int Cc)
{
    __shared__ __nv_bfloat16 tile[32][34];
    const size_t zoff = (size_t)blockIdx.z * R * Cc;
    in += zoff; out += zoff;
    const int r0 = blockIdx.x * 32, c0 = blockIdx.y * 32;
    const int tx = threadIdx.x, ty = threadIdx.y;
#pragma unroll
    for (int j = 0; j < 32; j += 8)
        tile[ty + j][tx] = in[(size_t)(r0 + ty + j) * Cc + c0 + tx];
    __syncthreads();
    const int t = ty * 32 + tx;
#pragma unroll
    for (int pidx = t; pidx < 512; pidx += 256) {
        const int oc = pidx >> 4;
        const int pr = (pidx & 15) * 2;
        __nv_bfloat16 h[2] = { tile[pr][oc], tile[pr + 1][oc] };
        size_t o = (size_t)(c0 + oc) * R + r0 + pr;
        *(uint32_t*)(out + o) = *(const uint32_t*)h;
    }
}

// =============== warp-MMA bf16 GEMM =========================================
// C[M,N] = A @ B^T. A:[M,K] K-major bf16, B:[N,K] K-major bf16.
// MODE 0: fp32 out Cf.
// MODE 2: p=ex2(acc) masked -> bf16 Cb + fixed-point row-sum atomics Zq
//         (alpha*log2e pre-folded into A).
// MODE 3: triple bf16 out (q|k|y segments of 384 cols) + per-seg bias; q seg
//         pre-scaled by QSCALE.
// CTA tile 128x128, 8 warps of 64x32, K chunk 32, 3-stage cp.async pipeline.
template<int MODE>
__global__ __launch_bounds__(256)
void gemm_bf16(const __nv_bfloat16* __restrict__ A, const __nv_bfloat16* __restrict__ Bm,
               float* __restrict__ Cf, __nv_bfloat16* __restrict__ Cb,
               __nv_bfloat16* __restrict__ Cb2, __nv_bfloat16* __restrict__ Cb3,
               const float* __restrict__ bias, const float* __restrict__ bias2,
               const float* __restrict__ bias3,
               const int* __restrict__ am, unsigned long long* __restrict__ Zq,
               int N, int K, size_t sA, size_t sB, size_t sC)
{
    extern __shared__ char smem[];
    const uint32_t sbase = smem_u32(smem);
    const int t = threadIdx.x;
    const int mBase = blockIdx.y * 128, nBase = blockIdx.x * 128;
    A  += (size_t)blockIdx.z * sA;
    Bm += (size_t)blockIdx.z * sB;

    const int lane = t & 31, w = t >> 5;
    const int mW = (w & 1) * 64, nW = (w >> 1) * 32;
    const uint32_t aOff = (uint32_t)(lane & 15) * LDSROW + (uint32_t)(lane >> 4) * 16;
    const uint32_t bOff = (uint32_t)(((lane >> 4) << 3) + (lane & 7)) * LDSROW
                        + (uint32_t)((lane >> 3) & 1) * 16;

    const int lrow0 = t >> 2,           lseg0 = t & 3;
    const int lrow1 = (t + 256) >> 2,   lseg1 = t & 3;

    float acc[4][4][4];
#pragma unroll
    for (int i = 0; i < 4; i++)
#pragma unroll
        for (int j = 0; j < 4; j++)
#pragma unroll
            for (int r = 0; r < 4; r++) acc[i][j][r] = 0.f;

    auto load_chunk = [&](int c, int buf) {
        const int kt = c * 32;
        const uint32_t bb = sbase + (uint32_t)buf * BUFB;
        cp16(bb + lrow0 * LDSROW + lseg0 * 16,
             A + (size_t)(mBase + lrow0) * K + kt + lseg0 * 8);
        cp16(bb + lrow1 * LDSROW + lseg1 * 16,
             A + (size_t)(mBase + lrow1) * K + kt + lseg1 * 8);
        cp16(bb + TILEB + lrow0 * LDSROW + lseg0 * 16,
             Bm + (size_t)(nBase + lrow0) * K + kt + lseg0 * 8);
        cp16(bb + TILEB + lrow1 * LDSROW + lseg1 * 16,
             Bm + (size_t)(nBase + lrow1) * K + kt + lseg1 * 8);
    };

    const int NC = K >> 5;

    load_chunk(0, 0); CP_COMMIT();
    load_chunk(1, 1); CP_COMMIT();

    int buf = 0;
    for (int c = 0; c < NC; c++) {
        if (c + 2 < NC) load_chunk(c + 2, (c + 2) % 3);
        CP_COMMIT();
        CP_WAIT2();
        __syncthreads();

        const uint32_t bb  = sbase + (uint32_t)buf * BUFB;
        const uint32_t bAh = bb + (uint32_t)mW * LDSROW;
        const uint32_t bBh = bb + TILEB + (uint32_t)nW * LDSROW;

#pragma unroll
        for (int ks = 0; ks < 2; ks++) {
            const uint32_t ko = (uint32_t)ks * 32;
            uint32_t aH[4][4], bH[4][2];
#pragma unroll
            for (int i = 0; i < 4; i++)
                LDSM4(aH[i], bAh + (uint32_t)(i * 16) * LDSROW + ko + aOff);
#pragma unroll
            for (int j = 0; j < 2; j++) {
                uint32_t r[4];
                LDSM4(r, bBh + (uint32_t)(j * 16) * LDSROW + ko + bOff);
                bH[2*j][0] = r[0]; bH[2*j][1] = r[1];
                bH[2*j+1][0] = r[2]; bH[2*j+1][1] = r[3];
            }
#pragma unroll
            for (int i = 0; i < 4; i++)
#pragma unroll
                for (int j = 0; j < 4; j++)
                    MMA16816(acc[i][j], aH[i], bH[j]);
        }
        __syncthreads();
        buf = (buf + 1 == 3) ? 0 : buf + 1;
    }

    // ---------------- epilogue ----------------------------------------------
    const int g = lane >> 2, tg2 = (lane & 3) * 2;
    if (MODE == 2) {
        // p = ex2(acc) with key mask (scale pre-folded into q); quad-reduced Z
        __nv_bfloat16* oc = Cb + (size_t)blockIdx.z * sC;
        const int* amb = am + (size_t)blockIdx.z * S_;
        unsigned long long* zb = Zq + (size_t)blockIdx.z * S_;
        bool m0a[4], m1a[4];
#pragma unroll
        for (int j = 0; j < 4; j++) {
            const int c0 = nBase + nW + j * 8 + tg2;
            m0a[j] = amb[c0] != 0; m1a[j] = amb[c0 + 1] != 0;
        }
#pragma unroll
        for (int i = 0; i < 4; i++) {
            const int r0 = mBase + mW + i * 16 + g, r1 = r0 + 8;
            float s0 = 0.f, s1 = 0.f;
#pragma unroll
            for (int j = 0; j < 4; j++) {
                const int c0 = nBase + nW + j * 8 + tg2;
                float e00 = m0a[j] ? ex2f(acc[i][j][0]) : 0.f;
                float e01 = m1a[j] ? ex2f(acc[i][j][1]) : 0.f;
                float e10 = m0a[j] ? ex2f(acc[i][j][2]) : 0.f;
                float e11 = m1a[j] ? ex2f(acc[i][j][3]) : 0.f;
                s0 += e00 + e01; s1 += e10 + e11;
                *(__nv_bfloat162*)(oc + (size_t)r0 * N + c0) =
                    __nv_bfloat162(__float2bfloat16(e00), __float2bfloat16(e01));
                *(__nv_bfloat162*)(oc + (size_t)r1 * N + c0) =
                    __nv_bfloat162(__float2bfloat16(e10), __float2bfloat16(e11));
            }
            s0 += __shfl_xor_sync(0xffffffffu, s0, 1);
            s0 += __shfl_xor_sync(0xffffffffu, s0, 2);
            s1 += __shfl_xor_sync(0xffffffffu, s1, 1);
            s1 += __shfl_xor_sync(0xffffffffu, s1, 2);
            if ((lane & 3) == 0) {
                atomicAdd(zb + r0, (unsigned long long)llrintf(s0 * ZSCALE));
                atomicAdd(zb + r1, (unsigned long long)llrintf(s1 * ZSCALE));
            }
        }
    } else if (MODE == 3) {
        // triple output: cols [0,384)=q (pre-scaled), [384,768)=k, [768,1152)=y
        const int seg  = blockIdx.x / 3;
        const int nLoc = (blockIdx.x % 3) * 128;
        __nv_bfloat16* oc = (seg == 0) ? Cb : (seg == 1) ? Cb2 : Cb3;
        const float* bs   = (seg == 0) ? bias : (seg == 1) ? bias2 : bias3;
        const float scl   = (seg == 0) ? QSCALE : 1.0f;
#pragma unroll
        for (int i = 0; i < 4; i++) {
            const int r0 = mBase + mW + i * 16 + g, r1 = r0 + 8;
#pragma unroll
            for (int j = 0; j < 4; j++) {
                const int c0 = nLoc + nW + j * 8 + tg2;
                const float b0 = bs[c0], b1 = bs[c0 + 1];
                __nv_bfloat16 h0 = __float2bfloat16((acc[i][j][0] + b0) * scl);
                __nv_bfloat16 h1 = __float2bfloat16((acc[i][j][1] + b1) * scl);
                *(__nv_bfloat162*)(oc + (size_t)r0 * HH_ + c0) = __nv_bfloat162(h0, h1);
                h0 = __float2bfloat16((acc[i][j][2] + b0) * scl);
                h1 = __float2bfloat16((acc[i][j][3] + b1) * scl);
                *(__nv_bfloat162*)(oc + (size_t)r1 * HH_ + c0) = __nv_bfloat162(h0, h1);
            }
        }
    } else {
        float* oc = Cf + (size_t)blockIdx.z * sC;
#pragma unroll
        for (int i = 0; i < 4; i++) {
            const int r0 = mBase + mW + i * 16 + g, r1 = r0 + 8;
#pragma unroll
            for (int j = 0; j < 4; j++) {
                const int c0 = nBase + nW + j * 8 + tg2;
                float2 va = make_float2(acc[i][j][0], acc[i][j][1]);
                float2 vb = make_float2(acc[i][j][2], acc[i][j][3]);
                *(float2*)(oc + (size_t)r0 * N + c0) = va;
                *(float2*)(oc + (size_t)r1 * N + c0) = vb;
            }
        }
    }
}

// ------- per-row 1/Z rescale + LayerNorm + ReLU + dot(W2) -> token score -----
__global__ __launch_bounds__(128)
void lnscore_kernel(const float* __restrict__ hpre, const unsigned long long* __restrict__ zq,
                    const float* __restrict__ g1, const float* __restrict__ be1,
                    const float* __restrict__ W2, const float* __restrict__ b2,
                    const int* __restrict__ am, float* __restrict__ ts)
{
    __shared__ float red[128];
    const int row = blockIdx.x, t = threadIdx.x;
    const float zf = (float)zq[row];
    const float invZ = zf > 0.f ? (ZSCALE / zf) : 0.f;
    const float* hr = hpre + (size_t)row * HH_;
    const float v0 = hr[t] * invZ, v1 = hr[t + 128] * invZ, v2 = hr[t + 256] * invZ;

    red[t] = v0 + v1 + v2; __syncthreads();
    for (int o = 64; o > 0; o >>= 1) { if (t < o) red[t] += red[t + o]; __syncthreads(); }
    const float mean = red[0] * (1.f / HH_);
    __syncthreads();

    const float d0 = v0 - mean, d1 = v1 - mean, d2 = v2 - mean;
    red[t] = d0 * d0 + d1 * d1 + d2 * d2; __syncthreads();
    for (int o = 64; o > 0; o >>= 1) { if (t < o) red[t] += red[t + o]; __syncthreads(); }
    const float inv = rsqrtf(red[0] * (1.f / HH_) + 1e-5f);
    __syncthreads();

    float sp = fmaxf(d0 * inv * g1[t]       + be1[t],       0.f) * W2[t]
             + fmaxf(d1 * inv * g1[t + 128] + be1[t + 128], 0.f) * W2[t + 128]
             + fmaxf(d2 * inv * g1[t + 256] + be1[t + 256], 0.f) * W2[t + 256];
    red[t] = sp; __syncthreads();
    for (int o = 64; o > 0; o >>= 1) { if (t < o) red[t] += red[t + o]; __syncthreads(); }
    if (t == 0) {
        float v = red[0] + b2[0];
        if (am[row] == 0) v = -10000.f;
        ts[row] = v;
    }
}

// ---------------- span search + mean pooling ---------------------------------
__global__ __launch_bounds__(256)
void span_pool_kernel(const float* __restrict__ ts, const int* __restrict__ am,
                      const float* __restrict__ x, float* __restrict__ pooled)
{
    __shared__ float sc[2048];
    __shared__ float cum[2049];
    __shared__ float part[256];
    __shared__ int   ired[256];
    __shared__ float bvs[256];
    __shared__ int   bis[256];
    __shared__ int   s_start, s_len;

    const int b = blockIdx.x, t = threadIdx.x;

    int vc = 0;
    for (int i = t; i < S_; i += 256) {
        sc[i] = ts[(size_t)b * S_ + i];
        vc += am[(size_t)b * S_ + i];
    }
    ired[t] = vc; __syncthreads();
    for (int o = 128; o > 0; o >>= 1) { if (t < o) ired[t] += ired[t + o]; __syncthreads(); }
    const int vl = ired[0];

    float ps = 0.f;
    for (int i = 0; i < 8; i++) ps += sc[t * 8 + i];
    part[t] = ps; __syncthreads();
    if (t == 0) {
        float run = 0.f;
        for (int i = 0; i < 256; i++) { float v = part[i]; part[i] = run; run += v; }
        cum[2048] = run;
    }
    __syncthreads();
    float run = part[t];
    for (int i = 0; i < 8; i++) { int idx = t * 8 + i; cum[idx] = run; run += sc[idx]; }
    __syncthreads();

    float bestV = -3.0e38f; int bestI = 0x7fffffff;
    for (int flat = t; flat < 18 * S_; flat += 256) {
        const int li = flat >> 11, start = flat & 2047;
        const int L = 3 + li, end = start + L;
        const int endc = end > S_ ? S_ : end;
        const float fL = (float)L;
        float avg = (cum[endc] - cum[start]) / fL + 0.01f * fL / 20.0f;
        if (end > vl) avg = -1e30f;
        if (avg > bestV) { bestV = avg; bestI = flat; }
    }
    bvs[t] = bestV; bis[t] = bestI; __syncthreads();
    for (int o = 128; o > 0; o >>= 1) {
        if (t < o) {
            if (bvs[t + o] > bvs[t] || (bvs[t + o] == bvs[t] && bis[t + o] < bis[t])) {
                bvs[t] = bvs[t + o]; bis[t] = bis[t + o];
            }
        }
        __syncthreads();
    }
    if (t == 0) {
        const int fi = bis[0];
        int start = fi & 2047, L = 3 + (fi >> 11);
        if (vl <= 3) { start = 0; L = vl; }
        s_start = start; s_len = L;
    }
    __syncthreads();

    const int start = s_start, L = s_len;
    const float inv = 1.0f / ((float)L + 1e-6f);
    for (int h = t; h < H_; h += 256) {
        float s = 0.f;
        for (int r = 0; r < L; r++) s += x[((size_t)b * S_ + start + r) * H_ + h];
        pooled[b * H_ + h] = s * inv;
    }
}

// ---------------- classification head ----------------------------------------
__global__ __launch_bounds__(384)
void head_kernel(const float* __restrict__ pooled, const float* __restrict__ x,
                 const float* __restrict__ Wc1, const float* __restrict__ bc1,
                 const float* __restrict__ g2, const float* __restrict__ be2,
                 const float* __restrict__ Wc2, const float* __restrict__ bc2,
                 const float* __restrict__ Mint,
                 const float* __restrict__ Wcls, const float* __restrict__ bcls,
                 float* __restrict__ out)
{
    __shared__ float pl[768];
    __shared__ float hc[384];
    __shared__ float cs[64];
    __shared__ float cp[64];
    __shared__ float red[512];
    const int b = blockIdx.x, t = threadIdx.x;

    for (int i = t; i < H_; i += 384) pl[i] = pooled[b * H_ + i];
    if (t < 128) red[384 + t] = 0.f;
    __syncthreads();

    float acc = bc1[t];
    for (int k = 0; k < H_; k++) acc += pl[k] * Wc1[(size_t)k * HH_ + t];

    red[t] = acc; __syncthreads();
    for (int o = 256; o > 0; o >>= 1) { if (t < o) red[t] += red[t + o]; __syncthreads(); }
    const float mean = red[0] * (1.f / HH_);
    __syncthreads();
    const float d = acc - mean;
    red[t] = d * d; __syncthreads();
    for (int o = 256; o > 0; o >>= 1) { if (t < o) red[t] += red[t + o]; __syncthreads(); }
    const float var = red[0] * (1.f / HH_);
    const float yn = d * rsqrtf(var + 1e-5f) * g2[t] + be2[t];
    hc[t] = fmaxf(yn, 0.f);
    __syncthreads();

    if (t < C_) {
        float c = bc2[t];
        for (int k = 0; k < HH_; k++) c += hc[k] * Wc2[(size_t)k * C_ + t];
        cs[t] = c;
    }
    __syncthreads();
    if (t < C_) {
        float add = cs[t];
        for (int i = 0; i < C_; i++) {
            const float m = 0.5f * (Mint[i * C_ + t] + Mint[t * C_ + i]);
            const float sg = 1.f / (1.f + expf(-m));
            add += cs[i] * sg;
        }
        cp[t] = 1.f / (1.f + expf(-add));
    }
    __syncthreads();
    if (t < L_) {
        float lg = bcls[t];
        for (int c = 0; c < C_; c++) lg += cp[c] * Wcls[c * L_ + t];
        const float* xr = x + (size_t)b * S_ * H_;
        for (int h = 0; h < H_; h++) lg += xr[h] * Wcls[(C_ + h) * L_ + t];
        out[b * L_ + t] = lg;
    }
}

// ---------------------------- launcher ---------------------------------------
extern "C" void kernel_launch(void* const* d_in, const int* in_sizes, int n_in,
                              void* d_out, int out_size)
{
    const float* x    = (const float*)d_in[0];
    const int*   am   = (const int*)  d_in[1];
    const float* Wq   = (const float*)d_in[2];
    const float* bq   = (const float*)d_in[3];
    const float* Wk   = (const float*)d_in[4];
    const float* bk   = (const float*)d_in[5];
    const float* W1   = (const float*)d_in[6];
    const float* b1   = (const float*)d_in[7];
    const float* g1   = (const float*)d_in[8];
    const float* be1  = (const float*)d_in[9];
    const float* W2   = (const float*)d_in[10];
    const float* b2   = (const float*)d_in[11];
    const float* Wc1  = (const float*)d_in[12];
    const float* bc1  = (const float*)d_in[13];
    const float* g2   = (const float*)d_in[14];
    const float* be2  = (const float*)d_in[15];
    const float* Wc2  = (const float*)d_in[16];
    const float* bc2  = (const float*)d_in[17];
    const float* Mint = (const float*)d_in[18];
    const float* Wcls = (const float*)d_in[19];
    const float* bcls = (const float*)d_in[20];
    float* out = (float*)d_out;

    __nv_bfloat16 *xhi, *qhi, *khi, *yhi, *phi, *yThi, *Wcat;
    unsigned long long* zq;
    float *hp, *tp, *pp;
    cudaGetSymbolAddress((void**)&xhi,  g_xhi);
    cudaGetSymbolAddress((void**)&qhi,  g_qhi);
    cudaGetSymbolAddress((void**)&khi,  g_khi);
    cudaGetSymbolAddress((void**)&yhi,  g_yhi);
    cudaGetSymbolAddress((void**)&phi,  g_phi);
    cudaGetSymbolAddress((void**)&zq,   g_Zq);
    cudaGetSymbolAddress((void**)&yThi, g_yThi);
    cudaGetSymbolAddress((void**)&Wcat, g_Wcat);
    cudaGetSymbolAddress((void**)&hp, g_hpre);
    cudaGetSymbolAddress((void**)&tp, g_ts);
    cudaGetSymbolAddress((void**)&pp, g_pool);

    cudaFuncSetAttribute(gemm_bf16<0>, cudaFuncAttributeMaxDynamicSharedMemorySize, GEMM_SMEM);
    cudaFuncSetAttribute(gemm_bf16<2>, cudaFuncAttributeMaxDynamicSharedMemorySize, GEMM_SMEM);
    cudaFuncSetAttribute(gemm_bf16<3>, cudaFuncAttributeMaxDynamicSharedMemorySize, GEMM_SMEM);

    // launch 1: zero Z accumulators
    cudaMemsetAsync(zq, 0, 32768 * sizeof(unsigned long long));

    // launch 2: weight transposes into concatenated [1152,768] bf16
    transpose_w_kernel<<<dim3(24, 12, 3), dim3(32, 8)>>>(Wq, Wk, W1, Wcat);

    // launch 3: x -> bf16
    cvt_bf16_kernel<<<25165824 / 2048, 256>>>(x, xhi);

    // launch 4: fused projections -> q (pre-scaled) | k | y bf16 (+bias)
    gemm_bf16<3><<<dim3(9, 256, 1), 256, GEMM_SMEM>>>(
        xhi, Wcat, nullptr, qhi, khi, yhi, bq, bk, b1,
        nullptr, nullptr, 1152, H_, 0, 0, 0);

    // launch 5 (profiled by ncu -s/-c): fused attn+exp
    gemm_bf16<2><<<dim3(16, 16, B_), 256, GEMM_SMEM>>>(
        qhi, khi, nullptr, phi, nullptr, nullptr, nullptr, nullptr, nullptr,
        am, zq, S_, HH_,
        (size_t)S_ * HH_, (size_t)S_ * HH_, (size_t)S_ * S_);

    // launch 6: y^T per batch (only needed by p@y)
    transpose_bb_kernel<<<dim3(64, 12, 16), dim3(32, 8)>>>(yhi, yThi, S_, HH_);

    // launch 7: h_pre_unnorm = p @ y
    gemm_bf16<0><<<dim3(3, 16, B_), 256, GEMM_SMEM>>>(
        phi, yThi, hp, nullptr, nullptr, nullptr, nullptr, nullptr, nullptr,
        nullptr, nullptr, HH_, S_,
        (size_t)S_ * S_, (size_t)HH_ * S_, (size_t)S_ * HH_);

    // launches 8-10: scores (with 1/Z rescale), span+pool, head
    lnscore_kernel<<<B_ * S_, 128>>>(hp, zq, g1, be1, W2, b2, am, tp);
    span_pool_kernel<<<B_, 256>>>(tp, am, x, pp);
    head_kernel<<<B_, 384>>>(pp, x, Wc1, bc1, g2, be2, Wc2, bc2, Mint, Wcls, bcls, out);
}

// round 16
// speedup vs baseline: 1.0026x; 1.0026x over previous
#include <cuda_runtime.h>
#include <cuda_bf16.h>
#include <math.h>
#include <stdint.h>

// Problem constants
#define B_  16
#define S_  2048
#define H_  768
#define HH_ 384
#define C_  64
#define L_  4

// q pre-scale: alpha * log2(e) folded into the q projection output
#define QSCALE (1.4426950408889634f / 19.595917942265423f)

// ---------------- scratch (static __device__ arrays; no allocation) ----------
__device__ __nv_bfloat16 g_xhi [25165824];     // x bf16        [B*S,H]
__device__ __nv_bfloat16 g_qhi [12582912];     // q bf16 (prescaled) [B*S,HH]
__device__ __nv_bfloat16 g_khi [12582912];     // k bf16        [B*S,HH]
__device__ __nv_bfloat16 g_yhi [12582912];     // y bf16        [B*S,HH]
__device__ __nv_bfloat16 g_phi [67108864];     // p=exp(attn) bf16 [B,S,S]
__device__ unsigned long long g_Zq[32768];     // fixed-point row sums of p
__device__ __nv_bfloat16 g_yThi[12582912];     // y^T bf16      [B,HH,S]
__device__ float         g_hpre[12582912];     // h_pre (unnormalized) [B*S,HH]
__device__ float         g_ts  [32768];
__device__ float         g_pool[12288];
__device__ __nv_bfloat16 g_Wcat[884736];       // [Wq|Wk|W1]^T bf16 [1152,768]

// ============================ PTX helpers ====================================
__device__ __forceinline__ uint32_t smem_u32(const void* p) {
    return (uint32_t)__cvta_generic_to_shared(p);
}

__device__ __forceinline__ float ex2f(float x) {
    float r; asm("ex2.approx.f32 %0, %1;" : "=f"(r) : "f"(x)); return r;
}

__device__ __forceinline__ void cp16(uint32_t dst, const void* src) {
    asm volatile("cp.async.cg.shared.global [%0], [%1], 16;" :: "r"(dst), "l"(src));
}
#define CP_COMMIT() asm volatile("cp.async.commit_group;" ::: "memory")
#define CP_WAIT2()  asm volatile("cp.async.wait_group 2;" ::: "memory")

#define LDSM4(r, addr) \
    asm volatile("ldmatrix.sync.aligned.m8n8.x4.shared.b16 {%0,%1,%2,%3}, [%4];" \
        : "=r"((r)[0]), "=r"((r)[1]), "=r"((r)[2]), "=r"((r)[3]) : "r"(addr))

#define MMA16816(d, a, b) \
    asm volatile("mma.sync.aligned.m16n8k16.row.col.f32.bf16.bf16.f32 " \
        "{%0,%1,%2,%3}, {%4,%5,%6,%7}, {%8,%9}, {%0,%1,%2,%3};" \
        : "+f"((d)[0]), "+f"((d)[1]), "+f"((d)[2]), "+f"((d)[3]) \
        : "r"((a)[0]), "r"((a)[1]), "r"((a)[2]), "r"((a)[3]), \
          "r"((b)[0]), "r"((b)[1]))

// SMEM tile geometry: 128 rows x 32 bf16 (64B data) padded to 80B/row
#define LDSROW 80
#define TILEB  (128 * LDSROW)         // 10240 B
#define BUFB   (2 * TILEB)            // A, B tiles = 20480 B
#define GEMM_SMEM (3 * BUFB)          // 3-stage pipeline = 61440 B

#define ZSCALE 1048576.0f             // 2^20 fixed point for deterministic Z

// =============== conversions ================================================
__global__ __launch_bounds__(256)
void cvt_bf16_kernel(const float* __restrict__ src, __nv_bfloat16* __restrict__ hi)
{
    const size_t i = ((size_t)blockIdx.x * 256 + threadIdx.x) * 8;
    float4 v0 = *(const float4*)(src + i);
    float4 v1 = *(const float4*)(src + i + 4);
    __nv_bfloat16 h[8];
    h[0] = __float2bfloat16(v0.x); h[1] = __float2bfloat16(v0.y);
    h[2] = __float2bfloat16(v0.z); h[3] = __float2bfloat16(v0.w);
    h[4] = __float2bfloat16(v1.x); h[5] = __float2bfloat16(v1.y);
    h[6] = __float2bfloat16(v1.z); h[7] = __float2bfloat16(v1.w);
    *(uint4*)(hi + i) = *(const uint4*)h;
}

// Wq/Wk/W1 [768,384] fp32 -> concatenated W^T [1152,768] bf16 (z picks weight)
__global__ __launch_bounds__(256)
void transpose_w_kernel(const float* __restrict__ Wq, const float* __restrict__ Wk,
                        const float* __restrict__ W1, __nv_bfloat16* __restrict__ out)
{
    __shared__ float tile[32][33];
    const float* in = (blockIdx.z == 0) ? Wq : (blockIdx.z == 1) ? Wk : W1;
    __nv_bfloat16* o = out + (size_t)blockIdx.z * (HH_ * H_);
    const int r0 = blockIdx.x * 32, c0 = blockIdx.y * 32;
    const int tx = threadIdx.x, ty = threadIdx.y;
#pragma unroll
    for (int j = 0; j < 32; j += 8)
        tile[ty + j][tx] = in[(size_t)(r0 + ty + j) * HH_ + c0 + tx];
    __syncthreads();
    const int t = ty * 32 + tx;
#pragma unroll
    for (int pidx = t; pidx < 512; pidx += 256) {
        const int oc = pidx >> 4;
        const int pr = (pidx & 15) * 2;
        __nv_bfloat16 h[2];
        h[0] = __float2bfloat16(tile[pr][oc]);
        h[1] = __float2bfloat16(tile[pr + 1][oc]);
        size_t off = (size_t)(c0 + oc) * H_ + r0 + pr;
        *(uint32_t*)(o + off) = *(const uint32_t*)h;
    }
}

// bf16 in [R, C] -> bf16 out [C, R]; per-z offset = z*R*C
__global__ __launch_bounds__(256)
void transpose_bb_kernel(const __nv_bfloat16* __restrict__ in,
                         __nv_bfloat16* __restrict__ out, int R, int Cc)
{
    __shared__ __nv_bfloat16 tile[32][34];
    const size_t zoff = (size_t)blockIdx.z * R * Cc;
    in += zoff; out += zoff;
    const int r0 = blockIdx.x * 32, c0 = blockIdx.y * 32;
    const int tx = threadIdx.x, ty = threadIdx.y;
#pragma unroll
    for (int j = 0; j < 32; j += 8)
        tile[ty + j][tx] = in[(size_t)(r0 + ty + j) * Cc + c0 + tx];
    __syncthreads();
    const int t = ty * 32 + tx;
#pragma unroll
    for (int pidx = t; pidx < 512; pidx += 256) {
        const int oc = pidx >> 4;
        const int pr = (pidx & 15) * 2;
        __nv_bfloat16 h[2] = { tile[pr][oc], tile[pr + 1][oc] };
        size_t o = (size_t)(c0 + oc) * R + r0 + pr;
        *(uint32_t*)(out + o) = *(const uint32_t*)h;
    }
}

// =============== warp-MMA bf16 GEMM =========================================
// C[M,N] = A @ B^T. A:[M,K] K-major bf16, B:[N,K] K-major bf16.
// MODE 0: fp32 out Cf.
// MODE 2: p=ex2(acc) masked -> bf16 Cb + fixed-point row-sum atomics Zq
//         (alpha*log2e pre-folded into A).
// MODE 3: triple bf16 out (q|k|y segments of 384 cols) + per-seg bias; q seg
//         pre-scaled by QSCALE.
// CTA tile 128x128, 8 warps of 64x32, K chunk 32, 3-stage cp.async pipeline.
template<int MODE>
__global__ __launch_bounds__(256)
void gemm_bf16(const __nv_bfloat16* __restrict__ A, const __nv_bfloat16* __restrict__ Bm,
               float* __restrict__ Cf, __nv_bfloat16* __restrict__ Cb,
               __nv_bfloat16* __restrict__ Cb2, __nv_bfloat16* __restrict__ Cb3,
               const float* __restrict__ bias, const float* __restrict__ bias2,
               const float* __restrict__ bias3,
               const int* __restrict__ am, unsigned long long* __restrict__ Zq,
               int N, int K, size_t sA, size_t sB, size_t sC)
{
    extern __shared__ char smem[];
    const uint32_t sbase = smem_u32(smem);
    const int t = threadIdx.x;
    const int mBase = blockIdx.y * 128, nBase = blockIdx.x * 128;
    A  += (size_t)blockIdx.z * sA;
    Bm += (size_t)blockIdx.z * sB;

    const int lane = t & 31, w = t >> 5;
    const int mW = (w & 1) * 64, nW = (w >> 1) * 32;
    const uint32_t aOff = (uint32_t)(lane & 15) * LDSROW + (uint32_t)(lane >> 4) * 16;
    const uint32_t bOff = (uint32_t)(((lane >> 4) << 3) + (lane & 7)) * LDSROW
                        + (uint32_t)((lane >> 3) & 1) * 16;

    const int lrow0 = t >> 2,           lseg0 = t & 3;
    const int lrow1 = (t + 256) >> 2,   lseg1 = t & 3;

    float acc[4][4][4];
#pragma unroll
    for (int i = 0; i < 4; i++)
#pragma unroll
        for (int j = 0; j < 4; j++)
#pragma unroll
            for (int r = 0; r < 4; r++) acc[i][j][r] = 0.f;

    auto load_chunk = [&](int c, int buf) {
        const int kt = c * 32;
        const uint32_t bb = sbase + (uint32_t)buf * BUFB;
        cp16(bb + lrow0 * LDSROW + lseg0 * 16,
             A + (size_t)(mBase + lrow0) * K + kt + lseg0 * 8);
        cp16(bb + lrow1 * LDSROW + lseg1 * 16,
             A + (size_t)(mBase + lrow1) * K + kt + lseg1 * 8);
        cp16(bb + TILEB + lrow0 * LDSROW + lseg0 * 16,
             Bm + (size_t)(nBase + lrow0) * K + kt + lseg0 * 8);
        cp16(bb + TILEB + lrow1 * LDSROW + lseg1 * 16,
             Bm + (size_t)(nBase + lrow1) * K + kt + lseg1 * 8);
    };

    const int NC = K >> 5;

    load_chunk(0, 0); CP_COMMIT();
    load_chunk(1, 1); CP_COMMIT();

    int buf = 0;
    for (int c = 0; c < NC; c++) {
        if (c + 2 < NC) load_chunk(c + 2, (c + 2) % 3);
        CP_COMMIT();
        CP_WAIT2();
        __syncthreads();

        const uint32_t bb  = sbase + (uint32_t)buf * BUFB;
        const uint32_t bAh = bb + (uint32_t)mW * LDSROW;
        const uint32_t bBh = bb + TILEB + (uint32_t)nW * LDSROW;

#pragma unroll
        for (int ks = 0; ks < 2; ks++) {
            const uint32_t ko = (uint32_t)ks * 32;
            uint32_t aH[4][4], bH[4][2];
#pragma unroll
            for (int i = 0; i < 4; i++)
                LDSM4(aH[i], bAh + (uint32_t)(i * 16) * LDSROW + ko + aOff);
#pragma unroll
            for (int j = 0; j < 2; j++) {
                uint32_t r[4];
                LDSM4(r, bBh + (uint32_t)(j * 16) * LDSROW + ko + bOff);
                bH[2*j][0] = r[0]; bH[2*j][1] = r[1];
                bH[2*j+1][0] = r[2]; bH[2*j+1][1] = r[3];
            }
#pragma unroll
            for (int i = 0; i < 4; i++)
#pragma unroll
                for (int j = 0; j < 4; j++)
                    MMA16816(acc[i][j], aH[i], bH[j]);
        }
        __syncthreads();
        buf = (buf + 1 == 3) ? 0 : buf + 1;
    }

    // ---------------- epilogue ----------------------------------------------
    const int g = lane >> 2, tg2 = (lane & 3) * 2;
    if (MODE == 2) {
        // p = ex2(acc) with key mask (scale pre-folded into q); quad-reduced Z
        __nv_bfloat16* oc = Cb + (size_t)blockIdx.z * sC;
        const int* amb = am + (size_t)blockIdx.z * S_;
        unsigned long long* zb = Zq + (size_t)blockIdx.z * S_;
        bool m0a[4], m1a[4];
#pragma unroll
        for (int j = 0; j < 4; j++) {
            const int c0 = nBase + nW + j * 8 + tg2;
            m0a[j] = amb[c0] != 0; m1a[j] = amb[c0 + 1] != 0;
        }
#pragma unroll
        for (int i = 0; i < 4; i++) {
            const int r0 = mBase + mW + i * 16 + g, r1 = r0 + 8;
            float s0 = 0.f, s1 = 0.f;
#pragma unroll
            for (int j = 0; j < 4; j++) {
                const int c0 = nBase + nW + j * 8 + tg2;
                float e00 = m0a[j] ? ex2f(acc[i][j][0]) : 0.f;
                float e01 = m1a[j] ? ex2f(acc[i][j][1]) : 0.f;
                float e10 = m0a[j] ? ex2f(acc[i][j][2]) : 0.f;
                float e11 = m1a[j] ? ex2f(acc[i][j][3]) : 0.f;
                s0 += e00 + e01; s1 += e10 + e11;
                *(__nv_bfloat162*)(oc + (size_t)r0 * N + c0) =
                    __nv_bfloat162(__float2bfloat16(e00), __float2bfloat16(e01));
                *(__nv_bfloat162*)(oc + (size_t)r1 * N + c0) =
                    __nv_bfloat162(__float2bfloat16(e10), __float2bfloat16(e11));
            }
            s0 += __shfl_xor_sync(0xffffffffu, s0, 1);
            s0 += __shfl_xor_sync(0xffffffffu, s0, 2);
            s1 += __shfl_xor_sync(0xffffffffu, s1, 1);
            s1 += __shfl_xor_sync(0xffffffffu, s1, 2);
            if ((lane & 3) == 0) {
                atomicAdd(zb + r0, (unsigned long long)llrintf(s0 * ZSCALE));
                atomicAdd(zb + r1, (unsigned long long)llrintf(s1 * ZSCALE));
            }
        }
    } else if (MODE == 3) {
        // triple output: cols [0,384)=q (pre-scaled), [384,768)=k, [768,1152)=y
        const int seg  = blockIdx.x / 3;
        const int nLoc = (blockIdx.x % 3) * 128;
        __nv_bfloat16* oc = (seg == 0) ? Cb : (seg == 1) ? Cb2 : Cb3;
        const float* bs   = (seg == 0) ? bias : (seg == 1) ? bias2 : bias3;
        const float scl   = (seg == 0) ? QSCALE : 1.0f;
#pragma unroll
        for (int i = 0; i < 4; i++) {
            const int r0 = mBase + mW + i * 16 + g, r1 = r0 + 8;
#pragma unroll
            for (int j = 0; j < 4; j++) {
                const int c0 = nLoc + nW + j * 8 + tg2;
                const float b0 = bs[c0], b1 = bs[c0 + 1];
                __nv_bfloat16 h0 = __float2bfloat16((acc[i][j][0] + b0) * scl);
                __nv_bfloat16 h1 = __float2bfloat16((acc[i][j][1] + b1) * scl);
                *(__nv_bfloat162*)(oc + (size_t)r0 * HH_ + c0) = __nv_bfloat162(h0, h1);
                h0 = __float2bfloat16((acc[i][j][2] + b0) * scl);
                h1 = __float2bfloat16((acc[i][j][3] + b1) * scl);
                *(__nv_bfloat162*)(oc + (size_t)r1 * HH_ + c0) = __nv_bfloat162(h0, h1);
            }
        }
    } else {
        float* oc = Cf + (size_t)blockIdx.z * sC;
#pragma unroll
        for (int i = 0; i < 4; i++) {
            const int r0 = mBase + mW + i * 16 + g, r1 = r0 + 8;
#pragma unroll
            for (int j = 0; j < 4; j++) {
                const int c0 = nBase + nW + j * 8 + tg2;
                float2 va = make_float2(acc[i][j][0], acc[i][j][1]);
                float2 vb = make_float2(acc[i][j][2], acc[i][j][3]);
                *(float2*)(oc + (size_t)r0 * N + c0) = va;
                *(float2*)(oc + (size_t)r1 * N + c0) = vb;
            }
        }
    }
}

// ------- per-row 1/Z rescale + LayerNorm + ReLU + dot(W2) -> token score -----
__global__ __launch_bounds__(128)
void lnscore_kernel(const float* __restrict__ hpre, const unsigned long long* __restrict__ zq,
                    const float* __restrict__ g1, const float* __restrict__ be1,
                    const float* __restrict__ W2, const float* __restrict__ b2,
                    const int* __restrict__ am, float* __restrict__ ts)
{
    __shared__ float red[128];
    const int row = blockIdx.x, t = threadIdx.x;
    const float zf = (float)zq[row];
    const float invZ = zf > 0.f ? (ZSCALE / zf) : 0.f;
    const float* hr = hpre + (size_t)row * HH_;
    const float v0 = hr[t] * invZ, v1 = hr[t + 128] * invZ, v2 = hr[t + 256] * invZ;

    red[t] = v0 + v1 + v2; __syncthreads();
    for (int o = 64; o > 0; o >>= 1) { if (t < o) red[t] += red[t + o]; __syncthreads(); }
    const float mean = red[0] * (1.f / HH_);
    __syncthreads();

    const float d0 = v0 - mean, d1 = v1 - mean, d2 = v2 - mean;
    red[t] = d0 * d0 + d1 * d1 + d2 * d2; __syncthreads();
    for (int o = 64; o > 0; o >>= 1) { if (t < o) red[t] += red[t + o]; __syncthreads(); }
    const float inv = rsqrtf(red[0] * (1.f / HH_) + 1e-5f);
    __syncthreads();

    float sp = fmaxf(d0 * inv * g1[t]       + be1[t],       0.f) * W2[t]
             + fmaxf(d1 * inv * g1[t + 128] + be1[t + 128], 0.f) * W2[t + 128]
             + fmaxf(d2 * inv * g1[t + 256] + be1[t + 256], 0.f) * W2[t + 256];
    red[t] = sp; __syncthreads();
    for (int o = 64; o > 0; o >>= 1) { if (t < o) red[t] += red[t + o]; __syncthreads(); }
    if (t == 0) {
        float v = red[0] + b2[0];
        if (am[row] == 0) v = -10000.f;
        ts[row] = v;
    }
}

// ---------------- span search + mean pooling ---------------------------------
__global__ __launch_bounds__(256)
void span_pool_kernel(const float* __restrict__ ts, const int* __restrict__ am,
                      const float* __restrict__ x, float* __restrict__ pooled)
{
    __shared__ float sc[2048];
    __shared__ float cum[2049];
    __shared__ float part[256];
    __shared__ int   ired[256];
    __shared__ float bvs[256];
    __shared__ int   bis[256];
    __shared__ int   s_start, s_len;

    const int b = blockIdx.x, t = threadIdx.x;

    int vc = 0;
    for (int i = t; i < S_; i += 256) {
        sc[i] = ts[(size_t)b * S_ + i];
        vc += am[(size_t)b * S_ + i];
    }
    ired[t] = vc; __syncthreads();
    for (int o = 128; o > 0; o >>= 1) { if (t < o) ired[t] += ired[t + o]; __syncthreads(); }
    const int vl = ired[0];

    float ps = 0.f;
    for (int i = 0; i < 8; i++) ps += sc[t * 8 + i];
    part[t] = ps; __syncthreads();
    if (t == 0) {
        float run = 0.f;
        for (int i = 0; i < 256; i++) { float v = part[i]; part[i] = run; run += v; }
        cum[2048] = run;
    }
    __syncthreads();
    float run = part[t];
    for (int i = 0; i < 8; i++) { int idx = t * 8 + i; cum[idx] = run; run += sc[idx]; }
    __syncthreads();

    float bestV = -3.0e38f; int bestI = 0x7fffffff;
    for (int flat = t; flat < 18 * S_; flat += 256) {
        const int li = flat >> 11, start = flat & 2047;
        const int L = 3 + li, end = start + L;
        const int endc = end > S_ ? S_ : end;
        const float fL = (float)L;
        float avg = (cum[endc] - cum[start]) / fL + 0.01f * fL / 20.0f;
        if (end > vl) avg = -1e30f;
        if (avg > bestV) { bestV = avg; bestI = flat; }
    }
    bvs[t] = bestV; bis[t] = bestI; __syncthreads();
    for (int o = 128; o > 0; o >>= 1) {
        if (t < o) {
            if (bvs[t + o] > bvs[t] || (bvs[t + o] == bvs[t] && bis[t + o] < bis[t])) {
                bvs[t] = bvs[t + o]; bis[t] = bis[t + o];
            }
        }
        __syncthreads();
    }
    if (t == 0) {
        const int fi = bis[0];
        int start = fi & 2047, L = 3 + (fi >> 11);
        if (vl <= 3) { start = 0; L = vl; }
        s_start = start; s_len = L;
    }
    __syncthreads();

    const int start = s_start, L = s_len;
    const float inv = 1.0f / ((float)L + 1e-6f);
    for (int h = t; h < H_; h += 256) {
        float s = 0.f;
        for (int r = 0; r < L; r++) s += x[((size_t)b * S_ + start + r) * H_ + h];
        pooled[b * H_ + h] = s * inv;
    }
}

// ---------------- classification head ----------------------------------------
__global__ __launch_bounds__(384)
void head_kernel(const float* __restrict__ pooled, const float* __restrict__ x,
                 const float* __restrict__ Wc1, const float* __restrict__ bc1,
                 const float* __restrict__ g2, const float* __restrict__ be2,
                 const float* __restrict__ Wc2, const float* __restrict__ bc2,
                 const float* __restrict__ Mint,
                 const float* __restrict__ Wcls, const float* __restrict__ bcls,
                 float* __restrict__ out)
{
    __shared__ float pl[768];
    __shared__ float hc[384];
    __shared__ float cs[64];
    __shared__ float cp[64];
    __shared__ float red[512];
    const int b = blockIdx.x, t = threadIdx.x;

    for (int i = t; i < H_; i += 384) pl[i] = pooled[b * H_ + i];
    if (t < 128) red[384 + t] = 0.f;
    __syncthreads();

    float acc = bc1[t];
    for (int k = 0; k < H_; k++) acc += pl[k] * Wc1[(size_t)k * HH_ + t];

    red[t] = acc; __syncthreads();
    for (int o = 256; o > 0; o >>= 1) { if (t < o) red[t] += red[t + o]; __syncthreads(); }
    const float mean = red[0] * (1.f / HH_);
    __syncthreads();
    const float d = acc - mean;
    red[t] = d * d; __syncthreads();
    for (int o = 256; o > 0; o >>= 1) { if (t < o) red[t] += red[t + o]; __syncthreads(); }
    const float var = red[0] * (1.f / HH_);
    const float yn = d * rsqrtf(var + 1e-5f) * g2[t] + be2[t];
    hc[t] = fmaxf(yn, 0.f);
    __syncthreads();

    if (t < C_) {
        float c = bc2[t];
        for (int k = 0; k < HH_; k++) c += hc[k] * Wc2[(size_t)k * C_ + t];
        cs[t] = c;
    }
    __syncthreads();
    if (t < C_) {
        float add = cs[t];
        for (int i = 0; i < C_; i++) {
            const float m = 0.5f * (Mint[i * C_ + t] + Mint[t * C_ + i]);
            const float sg = 1.f / (1.f + expf(-m));
            add += cs[i] * sg;
        }
        cp[t] = 1.f / (1.f + expf(-add));
    }
    __syncthreads();
    if (t < L_) {
        float lg = bcls[t];
        for (int c = 0; c < C_; c++) lg += cp[c] * Wcls[c * L_ + t];
        const float* xr = x + (size_t)b * S_ * H_;
        for (int h = 0; h < H_; h++) lg += xr[h] * Wcls[(C_ + h) * L_ + t];
        out[b * L_ + t] = lg;
    }
}

// ---------------------------- launcher ---------------------------------------
extern "C" void kernel_launch(void* const* d_in, const int* in_sizes, int n_in,
                              void* d_out, int out_size)
{
    const float* x    = (const float*)d_in[0];
    const int*   am   = (const int*)  d_in[1];
    const float* Wq   = (const float*)d_in[2];
    const float* bq   = (const float*)d_in[3];
    const float* Wk   = (const float*)d_in[4];
    const float* bk   = (const float*)d_in[5];
    const float* W1   = (const float*)d_in[6];
    const float* b1   = (const float*)d_in[7];
    const float* g1   = (const float*)d_in[8];
    const float* be1  = (const float*)d_in[9];
    const float* W2   = (const float*)d_in[10];
    const float* b2   = (const float*)d_in[11];
    const float* Wc1  = (const float*)d_in[12];
    const float* bc1  = (const float*)d_in[13];
    const float* g2   = (const float*)d_in[14];
    const float* be2  = (const float*)d_in[15];
    const float* Wc2  = (const float*)d_in[16];
    const float* bc2  = (const float*)d_in[17];
    const float* Mint = (const float*)d_in[18];
    const float* Wcls = (const float*)d_in[19];
    const float* bcls = (const float*)d_in[20];
    float* out = (float*)d_out;

    __nv_bfloat16 *xhi, *qhi, *khi, *yhi, *phi, *yThi, *Wcat;
    unsigned long long* zq;
    float *hp, *tp, *pp;
    cudaGetSymbolAddress((void**)&xhi,  g_xhi);
    cudaGetSymbolAddress((void**)&qhi,  g_qhi);
    cudaGetSymbolAddress((void**)&khi,  g_khi);
    cudaGetSymbolAddress((void**)&yhi,  g_yhi);
    cudaGetSymbolAddress((void**)&phi,  g_phi);
    cudaGetSymbolAddress((void**)&zq,   g_Zq);
    cudaGetSymbolAddress((void**)&yThi, g_yThi);
    cudaGetSymbolAddress((void**)&Wcat, g_Wcat);
    cudaGetSymbolAddress((void**)&hp, g_hpre);
    cudaGetSymbolAddress((void**)&tp, g_ts);
    cudaGetSymbolAddress((void**)&pp, g_pool);

    cudaFuncSetAttribute(gemm_bf16<0>, cudaFuncAttributeMaxDynamicSharedMemorySize, GEMM_SMEM);
    cudaFuncSetAttribute(gemm_bf16<2>, cudaFuncAttributeMaxDynamicSharedMemorySize, GEMM_SMEM);
    cudaFuncSetAttribute(gemm_bf16<3>, cudaFuncAttributeMaxDynamicSharedMemorySize, GEMM_SMEM);

    // launch 1: zero Z accumulators
    cudaMemsetAsync(zq, 0, 32768 * sizeof(unsigned long long));

    // launch 2: weight transposes into concatenated [1152,768] bf16
    transpose_w_kernel<<<dim3(24, 12, 3), dim3(32, 8)>>>(Wq, Wk, W1, Wcat);

    // launch 3: x -> bf16
    cvt_bf16_kernel<<<25165824 / 2048, 256>>>(x, xhi);

    // launch 4: fused projections -> q (pre-scaled) | k | y bf16 (+bias)
    gemm_bf16<3><<<dim3(9, 256, 1), 256, GEMM_SMEM>>>(
        xhi, Wcat, nullptr, qhi, khi, yhi, bq, bk, b1,
        nullptr, nullptr, 1152, H_, 0, 0, 0);

    // launch 5 (profiled by ncu -s/-c): fused attn+exp
    gemm_bf16<2><<<dim3(16, 16, B_), 256, GEMM_SMEM>>>(
        qhi, khi, nullptr, phi, nullptr, nullptr, nullptr, nullptr, nullptr,
        am, zq, S_, HH_,
        (size_t)S_ * HH_, (size_t)S_ * HH_, (size_t)S_ * S_);

    // launch 6: y^T per batch (only needed by p@y)
    transpose_bb_kernel<<<dim3(64, 12, 16), dim3(32, 8)>>>(yhi, yThi, S_, HH_);

    // launch 7: h_pre_unnorm = p @ y
    gemm_bf16<0><<<dim3(3, 16, B_), 256, GEMM_SMEM>>>(
        phi, yThi, hp, nullptr, nullptr, nullptr, nullptr, nullptr, nullptr,
        nullptr, nullptr, HH_, S_,
        (size_t)S_ * S_, (size_t)HH_ * S_, (size_t)S_ * HH_);

    // launches 8-10: scores (with 1/Z rescale), span+pool, head
    lnscore_kernel<<<B_ * S_, 128>>>(hp, zq, g1, be1, W2, b2, am, tp);
    span_pool_kernel<<<B_, 256>>>(tp, am, x, pp);
    head_kernel<<<B_, 384>>>(pp, x, Wc1, bc1, g2, be2, Wc2, bc2, Mint, Wcls, bcls, out);
}